// round 3
// baseline (speedup 1.0000x reference)
#include <cuda_runtime.h>

#define BB 64
#define NP 1024
#define LL 64
#define HH 128
#define W1K 67           // 3 + L (W1 row length)
#define ROW 132          // padded smem row (floats)
#define TN 128           // points per MLP tile

__device__ float g_acc[3];        // [0]=chamfer dir0, [1]=dir1, [2]=l2
__device__ float g_w1l[BB * HH];  // per-batch latent part of layer 1 + b1

__global__ void init_kernel() {
    if (threadIdx.x < 3) g_acc[threadIdx.x] = 0.0f;
}

// W1L[b][o] = b1[o] + sum_l W1[o][3+l] * latent[b][l]
__global__ void __launch_bounds__(128) w1l_kernel(
    const float* __restrict__ latent, const float* __restrict__ W1,
    const float* __restrict__ b1)
{
    __shared__ float slat[LL];
    const int b = blockIdx.x, o = threadIdx.x;
    if (o < LL) slat[o] = latent[b * LL + o];
    __syncthreads();
    float acc = b1[o];
    const float* wrow = W1 + o * W1K + 3;
    #pragma unroll 8
    for (int l = 0; l < LL; l++) acc = fmaf(wrow[l], slat[l], acc);
    g_w1l[b * HH + o] = acc;
}

__device__ __forceinline__ float block_sum(float v, float* scratch) {
    #pragma unroll
    for (int off = 16; off; off >>= 1) v += __shfl_down_sync(0xffffffffu, v, off);
    int lane = threadIdx.x & 31, w = threadIdx.x >> 5;
    if (lane == 0) scratch[w] = v;
    __syncthreads();
    int nw = blockDim.x >> 5;
    v = (threadIdx.x < nw) ? scratch[threadIdx.x] : 0.0f;
    if (w == 0) {
        #pragma unroll
        for (int off = 16; off; off >>= 1) v += __shfl_down_sync(0xffffffffu, v, off);
    }
    return v;  // valid on thread 0
}

// ---------------------------------------------------------------------------
// MLP: h1 = relu(W1pc @ pc + W1L[b]); h2 = relu(W2 @ h1 + b2);
// noise = W3 @ h2 + b3; pc_est = pc - noise; accumulate L2 loss.
// One CTA = 128 points of one batch. 256 threads, 8x8 microtiles.
// ---------------------------------------------------------------------------
__global__ void __launch_bounds__(256) mlp_kernel(
    const float* __restrict__ pc, const float* __restrict__ pc_gt,
    const float* __restrict__ W1,
    const float* __restrict__ W2, const float* __restrict__ b2,
    const float* __restrict__ W3, const float* __restrict__ b3,
    float* __restrict__ out_est)
{
    extern __shared__ float sm[];
    float* s_w2 = sm;                    // [HH][ROW]  W2^T: [k][o]
    float* s_h  = sm + HH * ROW;         // [HH][ROW]  h1 then h2, [k][n]
    float* s_wx = s_h + HH * ROW;        // [3][ROW]   W1 pc-part, [k][o]
    float* s_x  = s_wx + 3 * ROW;        // [3][ROW]   pc tile, [k][n]
    float* s_e  = s_x + 3 * ROW;
    float* swl  = s_e;            // 128 : W1L row for this batch
    float* sb2  = s_e + 128;      // 128
    float* sw3  = s_e + 256;      // 384
    float* sb3  = s_e + 640;      // 4
    float* sred = s_e + 644;      // 32

    const int tid = threadIdx.x;
    const int b   = blockIdx.x >> 3;
    const int n0  = (blockIdx.x & 7) * TN;

    // ---- stage: pc tile, W1 pc-columns, W1L, W2^T, b2, W3, b3 ----
    for (int i = tid; i < 3 * TN; i += 256) {
        int k = i >> 7, n = i & 127;
        s_x[k * ROW + n] = pc[(b * 3 + k) * NP + n0 + n];
    }
    if (tid < 128) {
        s_wx[0 * ROW + tid] = W1[tid * W1K + 0];
        s_wx[1 * ROW + tid] = W1[tid * W1K + 1];
        s_wx[2 * ROW + tid] = W1[tid * W1K + 2];
        swl[tid] = g_w1l[b * HH + tid];
        sb2[tid] = b2[tid];
    }
    for (int i = tid; i < 384; i += 256) sw3[i] = W3[i];
    if (tid < 3) sb3[tid] = b3[tid];
    for (int i = tid; i < HH * HH; i += 256) {
        int o = i >> 7, k = i & 127;
        s_w2[k * ROW + o] = W2[i];
    }
    __syncthreads();

    const int tn = (tid & 15) * 8;
    const int to = (tid >> 4) * 8;

    float acc[8][8];
    #pragma unroll
    for (int i = 0; i < 8; i++)
        #pragma unroll
        for (int j = 0; j < 8; j++) acc[i][j] = 0.0f;

    // ---- layer 1: 3-deep GEMM + precomputed latent term ----
    #pragma unroll
    for (int k = 0; k < 3; k++) {
        float4 a0 = *(const float4*)&s_wx[k * ROW + to];
        float4 a1 = *(const float4*)&s_wx[k * ROW + to + 4];
        float4 c0 = *(const float4*)&s_x[k * ROW + tn];
        float4 c1 = *(const float4*)&s_x[k * ROW + tn + 4];
        float a[8] = {a0.x, a0.y, a0.z, a0.w, a1.x, a1.y, a1.z, a1.w};
        float c[8] = {c0.x, c0.y, c0.z, c0.w, c1.x, c1.y, c1.z, c1.w};
        #pragma unroll
        for (int i = 0; i < 8; i++)
            #pragma unroll
            for (int j = 0; j < 8; j++) acc[i][j] = fmaf(a[i], c[j], acc[i][j]);
    }
    #pragma unroll
    for (int i = 0; i < 8; i++) {
        float bi = swl[to + i];
        #pragma unroll
        for (int j = 0; j < 8; j++)
            s_h[(to + i) * ROW + tn + j] = fmaxf(acc[i][j] + bi, 0.0f);
    }
    __syncthreads();

    #pragma unroll
    for (int i = 0; i < 8; i++)
        #pragma unroll
        for (int j = 0; j < 8; j++) acc[i][j] = 0.0f;

    // ---- layer 2: 128x128x128 GEMM ----
    for (int k = 0; k < HH; k++) {
        float4 a0 = *(const float4*)&s_w2[k * ROW + to];
        float4 a1 = *(const float4*)&s_w2[k * ROW + to + 4];
        float4 c0 = *(const float4*)&s_h[k * ROW + tn];
        float4 c1 = *(const float4*)&s_h[k * ROW + tn + 4];
        float a[8] = {a0.x, a0.y, a0.z, a0.w, a1.x, a1.y, a1.z, a1.w};
        float c[8] = {c0.x, c0.y, c0.z, c0.w, c1.x, c1.y, c1.z, c1.w};
        #pragma unroll
        for (int i = 0; i < 8; i++)
            #pragma unroll
            for (int j = 0; j < 8; j++) acc[i][j] = fmaf(a[i], c[j], acc[i][j]);
    }
    __syncthreads();   // all h1 reads done; overwrite s_h with h2
    #pragma unroll
    for (int i = 0; i < 8; i++) {
        float bi = sb2[to + i];
        #pragma unroll
        for (int j = 0; j < 8; j++)
            s_h[(to + i) * ROW + tn + j] = fmaxf(acc[i][j] + bi, 0.0f);
    }
    __syncthreads();

    // ---- layer 3 (3x128) + epilogue: pc_est + L2 partial ----
    float l2v = 0.0f;
    if (tid < TN) {
        int n = tid, g = n0 + n;
        float o0 = sb3[0], o1 = sb3[1], o2 = sb3[2];
        #pragma unroll 4
        for (int k = 0; k < HH; k++) {
            float hv = s_h[k * ROW + n];
            o0 = fmaf(sw3[k], hv, o0);
            o1 = fmaf(sw3[128 + k], hv, o1);
            o2 = fmaf(sw3[256 + k], hv, o2);
        }
        int base = (b * 3) * NP + g;
        float e0 = pc[base] - o0;
        float e1 = pc[base + NP] - o1;
        float e2 = pc[base + 2 * NP] - o2;
        out_est[base] = e0;
        out_est[base + NP] = e1;
        out_est[base + 2 * NP] = e2;
        float d0 = pc_gt[base] - e0;
        float d1 = pc_gt[base + NP] - e1;
        float d2 = pc_gt[base + 2 * NP] - e2;
        l2v = fmaf(d0, d0, fmaf(d1, d1, d2 * d2));
    }
    __syncthreads();
    float s = block_sum(l2v, sred);
    if (tid == 0) atomicAdd(&g_acc[2], s);
}

// ---------------------------------------------------------------------------
// Chamfer: per row point, min squared distance to opposing cloud (in smem).
// grid = (4 row-tiles, 64 batches, 2 directions), 256 threads.
// ---------------------------------------------------------------------------
__global__ void __launch_bounds__(256) chamfer_kernel(
    const float* __restrict__ pc_gt, const float* __restrict__ est)
{
    __shared__ float sx[NP], sy[NP], sz[NP];
    __shared__ float sred[8];
    const int b = blockIdx.y;
    const int dir = blockIdx.z;
    const float* rows  = dir ? est   : pc_gt;
    const float* other = dir ? pc_gt : est;
    const int base = b * 3 * NP;

    for (int i = threadIdx.x; i < NP; i += 256) {
        sx[i] = other[base + i];
        sy[i] = other[base + NP + i];
        sz[i] = other[base + 2 * NP + i];
    }
    __syncthreads();

    const int n = blockIdx.x * 256 + threadIdx.x;
    const float ax = rows[base + n];
    const float ay = rows[base + NP + n];
    const float az = rows[base + 2 * NP + n];
    float best = 3.4e38f;
    #pragma unroll 8
    for (int m = 0; m < NP; m++) {
        float dx = ax - sx[m];
        float dy = ay - sy[m];
        float dz = az - sz[m];
        float d = fmaf(dx, dx, fmaf(dy, dy, dz * dz));
        best = fminf(best, d);
    }
    float s = block_sum(best, sred);
    if (threadIdx.x == 0) atomicAdd(&g_acc[dir], s);
}

__global__ void final_kernel(float* __restrict__ out) {
    float ch = (g_acc[0] + g_acc[1]) * (1.0f / (float)(BB * NP));
    float l2 = g_acc[2] * (1.0f / (float)(BB * 3 * NP));
    out[0] = 0.1f * ch + 0.9f * l2;
    out[1] = ch;
    out[2] = l2;
}

extern "C" void kernel_launch(void* const* d_in, const int* in_sizes, int n_in,
                              void* d_out, int out_size) {
    const float* pc    = (const float*)d_in[0];
    const float* pc_gt = (const float*)d_in[1];
    const float* lat   = (const float*)d_in[2];
    const float* W1    = (const float*)d_in[3];
    const float* b1    = (const float*)d_in[4];
    const float* W2    = (const float*)d_in[5];
    const float* b2    = (const float*)d_in[6];
    const float* W3    = (const float*)d_in[7];
    const float* b3    = (const float*)d_in[8];
    float* out = (float*)d_out;

    size_t smem = (size_t)(2 * HH * ROW + 6 * ROW + 676) * sizeof(float);
    // Sticky per-function attribute; ignore result (idempotent after the
    // first (non-captured) correctness call).
    (void)cudaFuncSetAttribute(mlp_kernel,
                               cudaFuncAttributeMaxDynamicSharedMemorySize,
                               (int)smem);

    init_kernel<<<1, 32>>>();
    w1l_kernel<<<BB, 128>>>(lat, W1, b1);
    mlp_kernel<<<BB * (NP / TN), 256, smem>>>(pc, pc_gt, W1, W2, b2, W3, b3,
                                              out + 3);
    chamfer_kernel<<<dim3(NP / 256, BB, 2), 256>>>(pc_gt, out + 3);
    final_kernel<<<1, 1>>>(out);
}